// round 4
// baseline (speedup 1.0000x reference)
#include <cuda_runtime.h>
#include <cuda_fp16.h>

#define B_   64
#define T_   512
#define D_   1024
#define H_   1024
#define L_   4
#define O_   256
#define NCTA 128
#define NTHR 256

// ---------------- scratch (static device globals; no allocation) ----------------
__device__ __half g_Wc[(size_t)L_ * 32 * 128 * 2048];   // [l][s][j=128][k=2048] fp16 fused Wih|Whh
__device__ __half g_xhi[(size_t)T_ * B_ * D_];          // x hi, layout [t][b][d]
__device__ __half g_xlo[(size_t)T_ * B_ * D_];          // x lo residual
__device__ __half g_hhi[2 * L_ * B_ * H_];              // h hi, [parity][l][b][h]
__device__ __half g_hlo[2 * L_ * B_ * H_];              // h lo
__device__ float  g_bias[L_ * 4 * H_];                  // bih + bhh
__device__ float  g_h3[B_ * H_];                        // final layer-3 h (fp32)
__device__ unsigned g_barGen;
__device__ unsigned g_barCnt;

// ---------------- grid barrier (all 128 CTAs resident: 1 CTA/SM, 128 <= 148) ----
__device__ __forceinline__ void gridBarrier() {
    __threadfence();                 // make this CTA's global writes visible (L2)
    __syncthreads();
    if (threadIdx.x == 0) {
        unsigned gen = *((volatile unsigned*)&g_barGen);
        __threadfence();             // order gen read before arrival
        unsigned prev = atomicAdd(&g_barCnt, 1u);
        if (prev == NCTA - 1) {
            g_barCnt = 0;
            __threadfence();
            atomicAdd(&g_barGen, 1u);
        } else {
            while (*((volatile unsigned*)&g_barGen) == gen) { }
        }
    }
    __syncthreads();
}

// ---------------- mma.sync m16n8k16 fp16 -> fp32 --------------------------------
__device__ __forceinline__ void mma16816(float* c, const unsigned* a, const unsigned* b) {
    asm volatile(
        "mma.sync.aligned.m16n8k16.row.col.f32.f16.f16.f32 "
        "{%0,%1,%2,%3}, {%4,%5,%6,%7}, {%8,%9}, {%0,%1,%2,%3};\n"
        : "+f"(c[0]), "+f"(c[1]), "+f"(c[2]), "+f"(c[3])
        : "r"(a[0]), "r"(a[1]), "r"(a[2]), "r"(a[3]), "r"(b[0]), "r"(b[1]));
}

// ---------------- prep: weight swizzle + x fp16 hi/lo + fused bias ---------------
__global__ void prep_kernel(const float* __restrict__ x,
                            const float* __restrict__ Wih,
                            const float* __restrict__ Whh,
                            const float* __restrict__ bih,
                            const float* __restrict__ bhh) {
    long long tid = (long long)blockIdx.x * blockDim.x + threadIdx.x;
    long long stride = (long long)gridDim.x * blockDim.x;

    const long long NW = (long long)L_ * 32 * 128 * 2048;   // 33,554,432
    for (long long n = tid; n < NW; n += stride) {
        int k = (int)(n & 2047);
        int j = (int)((n >> 11) & 127);
        int s = (int)((n >> 18) & 31);
        int l = (int)(n >> 23);
        int g = j >> 5, jj = j & 31;
        int row = g * 1024 + s * 32 + jj;
        float v = (k < 1024)
            ? Wih[((long long)l * 4096 + row) * 1024 + k]
            : Whh[((long long)l * 4096 + row) * 1024 + (k - 1024)];
        g_Wc[n] = __float2half_rn(v);
    }

    const long long NX = (long long)T_ * B_ * D_;           // 33,554,432
    for (long long n = tid; n < NX; n += stride) {
        int d = (int)(n & 1023);
        int b = (int)((n >> 10) & 63);
        int t = (int)(n >> 16);
        float v = x[((long long)b * T_ + t) * D_ + d];
        __half hi = __float2half_rn(v);
        __half lo = __float2half_rn(v - __half2float(hi));
        g_xhi[n] = hi;
        g_xlo[n] = lo;
    }

    for (long long n = tid; n < L_ * 4 * H_; n += stride)
        g_bias[n] = bih[n] + bhh[n];
}

// ---------------- persistent LSTM kernel -----------------------------------------
__global__ void __launch_bounds__(NTHR, 1) lstm_kernel() {
    const int tid = threadIdx.x;
    const int bid = blockIdx.x;
    const int l = bid >> 5;          // layer 0..3
    const int s = bid & 31;          // h-column slice: cols [s*32, s*32+32)

    // SMEM: staging (W 128x72, Ahi 64x72, Alo 64x72 halves) unioned with gates (4x64x32 f32)
    __shared__ __align__(16) unsigned char sbuf[36864];
    __shared__ float sCst[B_ * 32];                    // persistent c state [b][hc]
    __half* sW   = (__half*)sbuf;                      // [128][72]
    __half* sAhi = (__half*)(sbuf + 18432);            // [64][72]
    __half* sAlo = (__half*)(sbuf + 27648);            // [64][72]
    float*  sG   = (float*)sbuf;                       // [4][64][32]

    // zero h double buffers (all CTAs) + c state
    {
        const int total = (2 * L_ * B_ * H_) / 8;      // uint4 count = 65536
        uint4 z = make_uint4(0, 0, 0, 0);
        for (int i = bid * NTHR + tid; i < total; i += NCTA * NTHR) {
            ((uint4*)g_hhi)[i] = z;
            ((uint4*)g_hlo)[i] = z;
        }
        for (int i = tid; i < B_ * 32; i += NTHR) sCst[i] = 0.f;
    }
    gridBarrier();

    const int wid = tid >> 5, lane = tid & 31;
    const int wm = wid >> 2;        // warp M tile (0..1) -> batch rows
    const int gn = wid & 3;         // warp N tile == gate index (i,f,g,o)
    const int mb = wm * 32;
    const int nb = gn * 32;
    const int grp = lane >> 2, tg = lane & 3;

    const __half* Wbase = g_Wc + ((long long)(l * 32 + s) * 128) * 2048;
    const float* bb = g_bias + l * 4096 + s * 32;

    for (int tau = 0; tau < T_ + L_ - 1; ++tau) {
        const int t = tau - l;
        if (t >= 0 && t < T_) {
            const int par = tau & 1;
            const __half* hin_hi = g_hhi + (par ^ 1) * (L_ * B_ * H_);
            const __half* hin_lo = g_hlo + (par ^ 1) * (L_ * B_ * H_);
            const __half* inhi, *inlo;
            if (l == 0) { inhi = g_xhi + (long long)t * (B_ * D_); inlo = g_xlo + (long long)t * (B_ * D_); }
            else        { inhi = hin_hi + (l - 1) * (B_ * H_);     inlo = hin_lo + (l - 1) * (B_ * H_); }
            const __half* rechi = hin_hi + l * (B_ * H_);
            const __half* reclo = hin_lo + l * (B_ * H_);

            float acc[2][4][4];
            #pragma unroll
            for (int mi = 0; mi < 2; ++mi)
                #pragma unroll
                for (int ni = 0; ni < 4; ++ni)
                    #pragma unroll
                    for (int q = 0; q < 4; ++q) acc[mi][ni][q] = 0.f;

            uint4 rw[4], rahi[2], ralo[2];

            auto load_chunk = [&](int kc) {
                const int kb = kc * 64;
                #pragma unroll
                for (int q = 0; q < 4; ++q) {
                    int flat = tid + q * 256; int j = flat >> 3, c8 = flat & 7;
                    rw[q] = __ldg((const uint4*)(Wbase + (long long)j * 2048 + kb + c8 * 8));
                }
                const __half* Ah; const __half* Al; int koff;
                if (kb < 1024) { Ah = inhi;  Al = inlo;  koff = kb; }
                else           { Ah = rechi; Al = reclo; koff = kb - 1024; }
                #pragma unroll
                for (int q = 0; q < 2; ++q) {
                    int flat = tid + q * 256; int b = flat >> 3, c8 = flat & 7;
                    rahi[q] = __ldcg((const uint4*)(Ah + (long long)b * 1024 + koff + c8 * 8));
                    ralo[q] = __ldcg((const uint4*)(Al + (long long)b * 1024 + koff + c8 * 8));
                }
            };
            auto store_chunk = [&]() {
                #pragma unroll
                for (int q = 0; q < 4; ++q) {
                    int flat = tid + q * 256; int j = flat >> 3, c8 = flat & 7;
                    *(uint4*)(sW + j * 72 + c8 * 8) = rw[q];
                }
                #pragma unroll
                for (int q = 0; q < 2; ++q) {
                    int flat = tid + q * 256; int b = flat >> 3, c8 = flat & 7;
                    *(uint4*)(sAhi + b * 72 + c8 * 8) = rahi[q];
                    *(uint4*)(sAlo + b * 72 + c8 * 8) = ralo[q];
                }
            };

            load_chunk(0); store_chunk(); __syncthreads();

            for (int kc = 0; kc < 32; ++kc) {
                if (kc + 1 < 32) load_chunk(kc + 1);    // prefetch to regs

                #pragma unroll
                for (int kk = 0; kk < 4; ++kk) {
                    const int k0 = kk * 16 + 2 * tg;
                    unsigned bfr[4][2];
                    #pragma unroll
                    for (int ni = 0; ni < 4; ++ni) {
                        const __half* p = sW + (nb + ni * 8 + grp) * 72 + k0;
                        bfr[ni][0] = *(const unsigned*)p;
                        bfr[ni][1] = *(const unsigned*)(p + 8);
                    }
                    unsigned ah[2][4], al[2][4];
                    #pragma unroll
                    for (int mi = 0; mi < 2; ++mi) {
                        const __half* p0 = sAhi + (mb + mi * 16 + grp) * 72 + k0;
                        ah[mi][0] = *(const unsigned*)p0;
                        ah[mi][1] = *(const unsigned*)(p0 + 8 * 72);
                        ah[mi][2] = *(const unsigned*)(p0 + 8);
                        ah[mi][3] = *(const unsigned*)(p0 + 8 * 72 + 8);
                        const __half* p1 = sAlo + (mb + mi * 16 + grp) * 72 + k0;
                        al[mi][0] = *(const unsigned*)p1;
                        al[mi][1] = *(const unsigned*)(p1 + 8 * 72);
                        al[mi][2] = *(const unsigned*)(p1 + 8);
                        al[mi][3] = *(const unsigned*)(p1 + 8 * 72 + 8);
                    }
                    #pragma unroll
                    for (int mi = 0; mi < 2; ++mi)
                        #pragma unroll
                        for (int ni = 0; ni < 4; ++ni)
                            mma16816(acc[mi][ni], ah[mi], bfr[ni]);
                    #pragma unroll
                    for (int mi = 0; mi < 2; ++mi)
                        #pragma unroll
                        for (int ni = 0; ni < 4; ++ni)
                            mma16816(acc[mi][ni], al[mi], bfr[ni]);
                }
                __syncthreads();
                if (kc + 1 < 32) store_chunk();
                __syncthreads();
            }

            // dump gate pre-activations to SMEM (overlays staging area; safe after syncs)
            #pragma unroll
            for (int mi = 0; mi < 2; ++mi)
                #pragma unroll
                for (int ni = 0; ni < 4; ++ni) {
                    int b0 = mb + mi * 16 + grp;
                    int c0 = ni * 8 + 2 * tg;
                    float* dst = sG + ((gn * 64 + b0) * 32 + c0);
                    dst[0]       = acc[mi][ni][0];
                    dst[1]       = acc[mi][ni][1];
                    dst[256]     = acc[mi][ni][2];   // b0 + 8
                    dst[257]     = acc[mi][ni][3];
                }
            __syncthreads();

            // elementwise LSTM cell; c persistent in SMEM; h -> global fp16 hi/lo
            __half* hout_hi = g_hhi + par * (L_ * B_ * H_) + l * (B_ * H_);
            __half* hout_lo = g_hlo + par * (L_ * B_ * H_) + l * (B_ * H_);
            for (int idx = tid; idx < B_ * 16; idx += NTHR) {  // pairs of hc
                int b = idx >> 4;
                int hc = (idx & 15) * 2;
                float h2[2];
                #pragma unroll
                for (int e = 0; e < 2; ++e) {
                    int c = hc + e;
                    float ai = sG[(0 * 64 + b) * 32 + c] + bb[0 * 1024 + c];
                    float af = sG[(1 * 64 + b) * 32 + c] + bb[1 * 1024 + c];
                    float ag = sG[(2 * 64 + b) * 32 + c] + bb[2 * 1024 + c];
                    float ao = sG[(3 * 64 + b) * 32 + c] + bb[3 * 1024 + c];
                    float ig = 1.f / (1.f + expf(-ai));
                    float fg = 1.f / (1.f + expf(-af));
                    float gg = tanhf(ag);
                    float og = 1.f / (1.f + expf(-ao));
                    float cs = fg * sCst[b * 32 + c] + ig * gg;
                    sCst[b * 32 + c] = cs;
                    h2[e] = og * tanhf(cs);
                }
                __half h0h = __float2half_rn(h2[0]);
                __half h1h = __float2half_rn(h2[1]);
                __half h0l = __float2half_rn(h2[0] - __half2float(h0h));
                __half h1l = __float2half_rn(h2[1] - __half2float(h1h));
                unsigned phi = (unsigned)__half_as_ushort(h0h) | ((unsigned)__half_as_ushort(h1h) << 16);
                unsigned plo = (unsigned)__half_as_ushort(h0l) | ((unsigned)__half_as_ushort(h1l) << 16);
                int go = b * 1024 + s * 32 + hc;
                __stcg((unsigned*)(hout_hi + go), phi);
                __stcg((unsigned*)(hout_lo + go), plo);
                if (l == 3 && t == T_ - 1) {
                    g_h3[go]     = h2[0];
                    g_h3[go + 1] = h2[1];
                }
            }
        }
        gridBarrier();
    }
}

// ---------------- final FC: out[b][o] = h3[b] . fc_w[o] + fc_b[o] ----------------
__global__ void fc_kernel(const float* __restrict__ fc_w,
                          const float* __restrict__ fc_b,
                          float* __restrict__ out) {
    __shared__ float hs[H_];
    const int b = blockIdx.x;
    const int o = threadIdx.x;      // 256 threads == O_
    for (int k = o; k < H_; k += O_) hs[k] = g_h3[b * H_ + k];
    __syncthreads();
    const float* w = fc_w + (long long)o * H_;
    float a0 = 0.f, a1 = 0.f, a2 = 0.f, a3 = 0.f;
    #pragma unroll 4
    for (int k = 0; k < H_; k += 4) {
        a0 += hs[k + 0] * __ldg(w + k + 0);
        a1 += hs[k + 1] * __ldg(w + k + 1);
        a2 += hs[k + 2] * __ldg(w + k + 2);
        a3 += hs[k + 3] * __ldg(w + k + 3);
    }
    out[b * O_ + o] = fc_b[o] + ((a0 + a1) + (a2 + a3));
}

// ---------------- launch ----------------------------------------------------------
extern "C" void kernel_launch(void* const* d_in, const int* in_sizes, int n_in,
                              void* d_out, int out_size) {
    (void)in_sizes; (void)n_in; (void)out_size;
    const float* x    = (const float*)d_in[0];
    const float* Wih  = (const float*)d_in[1];
    const float* Whh  = (const float*)d_in[2];
    const float* bih  = (const float*)d_in[3];
    const float* bhh  = (const float*)d_in[4];
    const float* fc_w = (const float*)d_in[5];
    const float* fc_b = (const float*)d_in[6];

    prep_kernel<<<2048, 256>>>(x, Wih, Whh, bih, bhh);
    lstm_kernel<<<NCTA, NTHR>>>();
    fc_kernel<<<B_, O_>>>(fc_w, fc_b, (float*)d_out);
}

// round 6
// speedup vs baseline: 2.2625x; 2.2625x over previous
#include <cuda_runtime.h>
#include <cuda_fp16.h>
#include <cstdint>

#define B_   64
#define T_   512
#define H_   1024
#define L_   4
#define O_   256
#define NCTA 128
#define NTHR 256

#define KC      128                       // K per chunk
#define NCHUNK  16                        // 2048 / 128
#define WSTG    32768                     // W tile 128 rows x 256B
#define ASTG    16384                     // A tile  64 rows x 256B
#define STG     (WSTG + ASTG)             // 49152 per stage
#define OFF_SG  (3 * STG)                 // 147456 : gate preacts 64x128 f32
#define OFF_SC  (OFF_SG + 64 * 128 * 4)   // 180224 : cell state 64x32 f32
#define SMEM_TOTAL (OFF_SC + 8192)        // 188416

// ---------------- scratch (static device globals; no allocation) ----------------
__device__ __half g_Wc[(size_t)L_ * 32 * 128 * 2048];  // [l][s][j=128][k=2048] fp16
__device__ __half g_x[(size_t)T_ * B_ * H_];           // x fp16, [t][b][d]
__device__ __half g_h[2 * L_ * B_ * H_];               // h fp16, [parity][l][b][h]
__device__ float  g_bias[L_ * 4 * H_];                 // bih + bhh
__device__ float  g_h3[B_ * H_];                       // final layer-3 h (fp32)
__device__ unsigned g_barGen;
__device__ unsigned g_barCnt;

// ---------------- helpers --------------------------------------------------------
__device__ __forceinline__ uint32_t smem_u32(const void* p) {
    uint32_t a;
    asm("{ .reg .u64 t; cvta.to.shared.u64 t, %1; cvt.u32.u64 %0, t; }" : "=r"(a) : "l"(p));
    return a;
}
__device__ __forceinline__ void cpa16(uint32_t dst, const void* src) {
    asm volatile("cp.async.cg.shared.global [%0], [%1], 16;" :: "r"(dst), "l"(src) : "memory");
}
__device__ __forceinline__ void cp_commit() {
    asm volatile("cp.async.commit_group;" ::: "memory");
}
__device__ __forceinline__ void cp_wait1() {
    asm volatile("cp.async.wait_group 1;" ::: "memory");
}
__device__ __forceinline__ void ldsm4(uint32_t* r, uint32_t a) {
    asm volatile("ldmatrix.sync.aligned.m8n8.x4.shared.b16 {%0,%1,%2,%3}, [%4];"
                 : "=r"(r[0]), "=r"(r[1]), "=r"(r[2]), "=r"(r[3]) : "r"(a));
}
__device__ __forceinline__ void mma16816(float* c, const uint32_t* a, const uint32_t* b) {
    asm volatile(
        "mma.sync.aligned.m16n8k16.row.col.f32.f16.f16.f32 "
        "{%0,%1,%2,%3}, {%4,%5,%6,%7}, {%8,%9}, {%0,%1,%2,%3};\n"
        : "+f"(c[0]), "+f"(c[1]), "+f"(c[2]), "+f"(c[3])
        : "r"(a[0]), "r"(a[1]), "r"(a[2]), "r"(a[3]), "r"(b[0]), "r"(b[1]));
}

// ---------------- grid barrier (128 CTAs, 1/SM, all resident) --------------------
__device__ __forceinline__ void gridBarrier() {
    __threadfence();
    __syncthreads();
    if (threadIdx.x == 0) {
        unsigned gen = *((volatile unsigned*)&g_barGen);
        __threadfence();
        unsigned prev = atomicAdd(&g_barCnt, 1u);
        if (prev == NCTA - 1) {
            g_barCnt = 0;
            __threadfence();
            atomicAdd(&g_barGen, 1u);
        } else {
            while (*((volatile unsigned*)&g_barGen) == gen) { }
        }
    }
    __syncthreads();
}

// ---------------- prep: weight swizzle + x fp16 + fused bias ---------------------
__global__ void prep_kernel(const float* __restrict__ x,
                            const float* __restrict__ Wih,
                            const float* __restrict__ Whh,
                            const float* __restrict__ bih,
                            const float* __restrict__ bhh) {
    long long tid = (long long)blockIdx.x * blockDim.x + threadIdx.x;
    long long stride = (long long)gridDim.x * blockDim.x;

    const long long NW = (long long)L_ * 32 * 128 * 2048;
    for (long long n = tid; n < NW; n += stride) {
        int k = (int)(n & 2047);
        int j = (int)((n >> 11) & 127);
        int s = (int)((n >> 18) & 31);
        int l = (int)(n >> 23);
        int g = j >> 5, jj = j & 31;
        int row = g * 1024 + s * 32 + jj;
        float v = (k < 1024)
            ? Wih[((long long)l * 4096 + row) * 1024 + k]
            : Whh[((long long)l * 4096 + row) * 1024 + (k - 1024)];
        g_Wc[n] = __float2half_rn(v);
    }

    const long long NX = (long long)T_ * B_ * H_;
    for (long long n = tid; n < NX; n += stride) {
        int d = (int)(n & 1023);
        int b = (int)((n >> 10) & 63);
        int t = (int)(n >> 16);
        g_x[n] = __float2half_rn(x[((long long)b * T_ + t) * H_ + d]);
    }

    for (long long n = tid; n < L_ * 4 * H_; n += stride)
        g_bias[n] = bih[n] + bhh[n];
}

// ---------------- persistent LSTM kernel -----------------------------------------
__global__ void __launch_bounds__(NTHR, 1) lstm_kernel() {
    extern __shared__ __align__(1024) char smem[];
    const uint32_t sb = smem_u32(smem);
    const int tid = threadIdx.x;
    const int lane = tid & 31;
    const int wid = tid >> 5;
    const int bid = blockIdx.x;
    const int l = bid >> 5;          // layer
    const int s = bid & 31;          // gate-column slice (32 h cols)

    float* sG = (float*)(smem + OFF_SG);  // [b=64][n=128]
    float* sC = (float*)(smem + OFF_SC);  // [b=64][hc=32]

    // zero h double buffer + c state
    {
        const int total = (2 * L_ * B_ * H_) / 8;     // uint4 count
        uint4 z = make_uint4(0, 0, 0, 0);
        for (int i = bid * NTHR + tid; i < total; i += NCTA * NTHR)
            ((uint4*)g_h)[i] = z;
        for (int i = tid; i < B_ * 32; i += NTHR) sC[i] = 0.f;
    }

    // elementwise constants
    const int hcl = tid & 31;
    const int eb0 = tid >> 5;
    float bias_g[4];
    #pragma unroll
    for (int g = 0; g < 4; ++g)
        bias_g[g] = g_bias[l * 4096 + g * 1024 + s * 32 + hcl];

    // warp / lane tiling for mma
    const int wm = wid >> 2;              // 0..1 : batch rows  [wm*32, +32)
    const int wn = wid & 3;               // 0..3 : gate rows   [wn*32, +32)
    const int t8 = lane >> 3;             // ldmatrix lane group 0..3
    const int r8 = lane & 7;
    const uint32_t swz = (uint32_t)r8;    // row&7 for both A and B tiles
    const uint32_t tA = (uint32_t)(t8 >> 1);
    const uint32_t tB = (uint32_t)(t8 & 1);

    uint32_t aBase[3][2], bBase[3][2];
    #pragma unroll
    for (int st = 0; st < 3; ++st) {
        uint32_t wa = sb + st * STG;
        #pragma unroll
        for (int mi = 0; mi < 2; ++mi) {
            int m = wm * 32 + mi * 16 + (t8 & 1) * 8 + r8;
            aBase[st][mi] = wa + WSTG + m * 256;
        }
        #pragma unroll
        for (int p = 0; p < 2; ++p) {
            int n = wn * 32 + p * 16 + (t8 >> 1) * 8 + r8;
            bBase[st][p] = wa + n * 256;
        }
    }

    const __half* Wbase = g_Wc + (size_t)(l * 32 + s) * 128 * 2048;

    gridBarrier();

    for (int tau = 0; tau < T_ + L_ - 1; ++tau) {
        const int t = tau - l;
        if (t >= 0 && t < T_) {
            const int par = tau & 1;
            const __half* hin = g_h + (par ^ 1) * (L_ * B_ * H_);
            const __half* in  = (l == 0) ? (g_x + (size_t)t * (B_ * H_))
                                         : (hin + (l - 1) * (B_ * H_));
            const __half* rec = hin + l * (B_ * H_);

            auto issueChunk = [&](int kc, int st) {
                const __half* Wsrc = Wbase + kc * KC;
                uint32_t wdst = sb + st * STG;
                #pragma unroll
                for (int q = 0; q < 8; ++q) {
                    int f = tid + q * 256;
                    int j = f >> 4, c16 = f & 15;
                    uint32_t d = wdst + (uint32_t)(j * 256) + ((uint32_t)(c16 ^ (j & 7)) << 4);
                    cpa16(d, Wsrc + (size_t)j * 2048 + c16 * 8);
                }
                const __half* Asrc = (kc < 8) ? in : rec;
                const int kloc = (kc & 7) * KC;
                uint32_t adst = wdst + WSTG;
                #pragma unroll
                for (int q = 0; q < 4; ++q) {
                    int f = tid + q * 256;
                    int b = f >> 4, c16 = f & 15;
                    uint32_t d = adst + (uint32_t)(b * 256) + ((uint32_t)(c16 ^ (b & 7)) << 4);
                    cpa16(d, Asrc + (size_t)b * 1024 + kloc + c16 * 8);
                }
            };

            float acc[2][4][4];
            #pragma unroll
            for (int mi = 0; mi < 2; ++mi)
                #pragma unroll
                for (int ni = 0; ni < 4; ++ni)
                    #pragma unroll
                    for (int q = 0; q < 4; ++q) acc[mi][ni][q] = 0.f;

            issueChunk(0, 0); cp_commit();
            issueChunk(1, 1); cp_commit();

            #pragma unroll
            for (int kc = 0; kc < NCHUNK; ++kc) {
                const int st = kc % 3;
                cp_wait1();            // chunk kc resident (this thread)
                __syncthreads();       // all threads' chunk kc resident; st buf reusable
                if (kc + 2 < NCHUNK) issueChunk(kc + 2, (kc + 2) % 3);
                cp_commit();           // (possibly empty group keeps counts aligned)

                #pragma unroll
                for (int kk = 0; kk < 8; ++kk) {
                    uint32_t a[2][4], bf[2][4];
                    #pragma unroll
                    for (int mi = 0; mi < 2; ++mi)
                        ldsm4(a[mi], aBase[st][mi] + ((((uint32_t)(2 * kk) + tA) ^ swz) << 4));
                    #pragma unroll
                    for (int p = 0; p < 2; ++p)
                        ldsm4(bf[p], bBase[st][p] + ((((uint32_t)(2 * kk) + tB) ^ swz) << 4));
                    #pragma unroll
                    for (int mi = 0; mi < 2; ++mi)
                        #pragma unroll
                        for (int p = 0; p < 2; ++p) {
                            mma16816(acc[mi][2 * p],     a[mi], &bf[p][0]);
                            mma16816(acc[mi][2 * p + 1], a[mi], &bf[p][2]);
                        }
                }
            }

            // ---- epilogue: acc -> sG[b][n] ----
            {
                const int grp = lane >> 2, tg = lane & 3;
                #pragma unroll
                for (int mi = 0; mi < 2; ++mi)
                    #pragma unroll
                    for (int ni = 0; ni < 4; ++ni) {
                        int n = wn * 32 + ni * 8 + tg * 2;
                        int m0 = wm * 32 + mi * 16 + grp;
                        *(float2*)&sG[m0 * 128 + n]       = make_float2(acc[mi][ni][0], acc[mi][ni][1]);
                        *(float2*)&sG[(m0 + 8) * 128 + n] = make_float2(acc[mi][ni][2], acc[mi][ni][3]);
                    }
            }
            __syncthreads();

            // ---- elementwise LSTM cell ----
            __half* hout = g_h + par * (L_ * B_ * H_) + l * (B_ * H_);
            #pragma unroll
            for (int b = eb0; b < 64; b += 8) {
                float ai = sG[b * 128 + 0 * 32 + hcl] + bias_g[0];
                float af = sG[b * 128 + 1 * 32 + hcl] + bias_g[1];
                float ag = sG[b * 128 + 2 * 32 + hcl] + bias_g[2];
                float ao = sG[b * 128 + 3 * 32 + hcl] + bias_g[3];
                float ig = 1.f / (1.f + expf(-ai));
                float fg = 1.f / (1.f + expf(-af));
                float gg = tanhf(ag);
                float og = 1.f / (1.f + expf(-ao));
                float cs = fg * sC[b * 32 + hcl] + ig * gg;
                sC[b * 32 + hcl] = cs;
                float hv = og * tanhf(cs);
                int go = b * 1024 + s * 32 + hcl;
                __stcg(hout + go, __float2half_rn(hv));
                if (l == 3 && t == T_ - 1) g_h3[go] = hv;
            }
        }
        gridBarrier();
    }
}

// ---------------- final FC: out[b][o] = h3[b] . fc_w[o] + fc_b[o] ----------------
__global__ void fc_kernel(const float* __restrict__ fc_w,
                          const float* __restrict__ fc_b,
                          float* __restrict__ out) {
    __shared__ float hs[H_];
    const int b = blockIdx.x;
    const int o = threadIdx.x;
    for (int k = o; k < H_; k += O_) hs[k] = g_h3[b * H_ + k];
    __syncthreads();
    const float* w = fc_w + (long long)o * H_;
    float a0 = 0.f, a1 = 0.f, a2 = 0.f, a3 = 0.f;
    #pragma unroll 4
    for (int k = 0; k < H_; k += 4) {
        a0 += hs[k + 0] * __ldg(w + k + 0);
        a1 += hs[k + 1] * __ldg(w + k + 1);
        a2 += hs[k + 2] * __ldg(w + k + 2);
        a3 += hs[k + 3] * __ldg(w + k + 3);
    }
    out[b * O_ + o] = fc_b[o] + ((a0 + a1) + (a2 + a3));
}

// ---------------- launch ----------------------------------------------------------
extern "C" void kernel_launch(void* const* d_in, const int* in_sizes, int n_in,
                              void* d_out, int out_size) {
    (void)in_sizes; (void)n_in; (void)out_size;
    const float* x    = (const float*)d_in[0];
    const float* Wih  = (const float*)d_in[1];
    const float* Whh  = (const float*)d_in[2];
    const float* bih  = (const float*)d_in[3];
    const float* bhh  = (const float*)d_in[4];
    const float* fc_w = (const float*)d_in[5];
    const float* fc_b = (const float*)d_in[6];

    cudaFuncSetAttribute(lstm_kernel, cudaFuncAttributeMaxDynamicSharedMemorySize, SMEM_TOTAL);
    prep_kernel<<<2048, 256>>>(x, Wih, Whh, bih, bhh);
    lstm_kernel<<<NCTA, NTHR, SMEM_TOTAL>>>();
    fc_kernel<<<B_, O_>>>(fc_w, fc_b, (float*)d_out);
}